// round 9
// baseline (speedup 1.0000x reference)
#include <cuda_runtime.h>
#include <math.h>

#define BSN 2500   // nodes
#define TT  400    // timesteps
#define DD  16     // input dim
#define HH  32     // hidden dim
#define G4  128    // 4*H

#define NCTA     125
#define ROWS     20          // 125*20 = 2500
#define NTHREADS 768
#define NWARP    24

// smem floats: adjT + red(4) + g4s + hs + cs + xs(double)
#define SMEM_FLOATS (BSN*ROWS + 4*ROWS*HH + ROWS*G4 + ROWS*HH + ROWS*HH + 2*ROWS*DD)
#define SMEM_BYTES  (SMEM_FLOATS * 4)

__device__ unsigned int g_bar;
__device__ float g_q[2][BSN * HH];   // double-buffered q_t

__device__ __forceinline__ unsigned long long pack2(float x, float y) {
    unsigned long long r;
    asm("mov.b64 %0, {%1, %2};" : "=l"(r) : "f"(x), "f"(y));
    return r;
}
__device__ __forceinline__ void ffma2(unsigned long long& d,
                                      unsigned long long a, unsigned long long b) {
    asm("fma.rn.f32x2 %0, %1, %2, %0;" : "+l"(d) : "l"(a), "l"(b));
}
__device__ __forceinline__ float2 unpack2(unsigned long long v) {
    float2 r;
    asm("mov.b64 {%0, %1}, %2;" : "=f"(r.x), "=f"(r.y) : "l"(v));
    return r;
}
__device__ __forceinline__ float sigmoid_f(float x) {
    return __fdividef(1.0f, 1.0f + __expf(-x));
}
__device__ __forceinline__ float tanh_f(float x) {
    return 1.0f - __fdividef(2.0f, __expf(2.0f * x) + 1.0f);
}

__device__ __forceinline__ void grid_barrier(unsigned epoch) {
    __threadfence();
    __syncthreads();
    if (threadIdx.x == 0) {
        atomicAdd(&g_bar, 1u);
        const unsigned target = epoch * (unsigned)NCTA;
        unsigned v;
        do {
            asm volatile("ld.acquire.gpu.global.u32 %0, [%1];"
                         : "=r"(v) : "l"(&g_bar) : "memory");
        } while (v < target);
    }
    __syncthreads();
}

// gates for step t, PRE-ACTIVATED into g4s: [i f g o] -> [sig sig tanh sig]
// 768 threads: j = tid&127, group g = tid>>7 (0..5) handles rows {g, g+6, g+12, g+18<20}
__device__ __forceinline__ void gates_act(
    int tid, const float* xcur, const float* hs, float* g4s,
    const float* __restrict__ W_ih, const float* __restrict__ W_hh,
    const float* __restrict__ b)
{
    const int j = tid & 127;
    const int g = tid >> 7;                 // 0..5
    const int nm = (g < 2) ? 4 : 3;         // rows in this group
    const int m3ok = (g + 18 < ROWS);
    float a4[4];
    const float bj = b[j];
    #pragma unroll
    for (int i = 0; i < 4; i++) a4[i] = bj;
    #pragma unroll
    for (int kk = 0; kk < HH; kk++) {
        const float w = W_hh[kk * G4 + j];
        a4[0] += hs[(g)      * HH + kk] * w;
        a4[1] += hs[(g + 6)  * HH + kk] * w;
        a4[2] += hs[(g + 12) * HH + kk] * w;
        a4[3] += hs[(m3ok ? (g + 18) : 0) * HH + kk] * w;
    }
    #pragma unroll
    for (int d = 0; d < DD; d++) {
        const float w = W_ih[d * G4 + j];
        a4[0] += xcur[(g)      * DD + d] * w;
        a4[1] += xcur[(g + 6)  * DD + d] * w;
        a4[2] += xcur[(g + 12) * DD + d] * w;
        a4[3] += xcur[(m3ok ? (g + 18) : 0) * DD + d] * w;
    }
    const int sect = j >> 5;   // 0:i 1:f 2:g 3:o
    #pragma unroll
    for (int i = 0; i < 4; i++) {
        if (i < nm) {
            const float v = (sect == 2) ? tanh_f(a4[i]) : sigmoid_f(a4[i]);
            g4s[(g + 6 * i) * G4 + j] = v;
        }
    }
}

// q_{t+1} = tanh(h@W_q + b_q) -> global (L2)
__device__ __forceinline__ void q_prep(
    int tid, int row0, const float* hs,
    const float* __restrict__ W_q, const float* __restrict__ b_q, float* qdst)
{
    for (int e = tid; e < ROWS * HH; e += NTHREADS) {
        const int m = e >> 5, n = e & 31;
        float a = b_q[n];
        #pragma unroll
        for (int kk = 0; kk < HH; kk++) a += hs[m * HH + kk] * W_q[kk * HH + n];
        __stcg(&qdst[(size_t)(row0 + m) * HH + n], tanh_f(a));
    }
}

__global__ void rgcn_reset() { g_bar = 0u; }

__global__ void __launch_bounds__(NTHREADS, 1)
rgcn_kernel(const float* __restrict__ x,    const float* __restrict__ adj,
            const float* __restrict__ W_ih, const float* __restrict__ W_hh,
            const float* __restrict__ b,    const float* __restrict__ W_q,
            const float* __restrict__ b_q,  const float* __restrict__ W_d,
            const float* __restrict__ b_d,  float* __restrict__ out)
{
    extern __shared__ float smem[];
    float* adjT  = smem;                    // [BSN][ROWS]
    float* red   = adjT + BSN * ROWS;       // [4][ROWS][HH]
    float* g4s   = red  + 4 * ROWS * HH;    // [ROWS][G4] (activated)
    float* hs    = g4s  + ROWS * G4;        // [ROWS][HH]
    float* cs    = hs   + ROWS * HH;        // [ROWS][HH]
    float* xsbuf = cs   + ROWS * HH;        // [2][ROWS][DD]

    const int tid  = threadIdx.x;
    const int lane = tid & 31;
    const int wid  = tid >> 5;
    const int row0 = blockIdx.x * ROWS;

    for (int e = tid; e < ROWS * HH; e += NTHREADS) { hs[e] = 0.0f; cs[e] = 0.0f; }
    for (int e = tid; e < ROWS * BSN; e += NTHREADS) {
        int m = e / BSN;
        int k = e - m * BSN;
        adjT[k * ROWS + m] = adj[(size_t)(row0 + m) * BSN + k];
    }
    for (int e = tid; e < ROWS * DD; e += NTHREADS)
        xsbuf[e] = x[(size_t)(row0 + e / DD) * (TT * DD) + (e & (DD - 1))];
    __syncthreads();

    // q_0 = tanh(0@W_q + b_q)
    q_prep(tid, row0, hs, W_q, b_q, g_q[0]);
    grid_barrier(1);

    const unsigned sA = (unsigned)__cvta_generic_to_shared(adjT);
    const int k0 = (BSN * wid) / NWARP;
    const int k1 = (BSN * (wid + 1)) / NWARP;

    for (int t = 0; t < TT; ++t) {
        const float* __restrict__ qr = g_q[t & 1];

        unsigned long long acc[ROWS / 2];
        #pragma unroll
        for (int i = 0; i < ROWS / 2; i++) acc[i] = 0ull;

        #define ADJ_FMA(KIDX, QQ) do {                                                  \
            unsigned a_off = sA + (unsigned)(KIDX) * (ROWS * 4u);                       \
            unsigned long long a0,a1,a2,a3,a4,a5,a6,a7,a8,a9;                           \
            asm("ld.shared.v2.b64 {%0,%1},[%2];" : "=l"(a0),"=l"(a1) : "r"(a_off));     \
            asm("ld.shared.v2.b64 {%0,%1},[%2];" : "=l"(a2),"=l"(a3) : "r"(a_off+16u)); \
            asm("ld.shared.v2.b64 {%0,%1},[%2];" : "=l"(a4),"=l"(a5) : "r"(a_off+32u)); \
            asm("ld.shared.v2.b64 {%0,%1},[%2];" : "=l"(a6),"=l"(a7) : "r"(a_off+48u)); \
            asm("ld.shared.v2.b64 {%0,%1},[%2];" : "=l"(a8),"=l"(a9) : "r"(a_off+64u)); \
            ffma2(acc[0], a0, QQ); ffma2(acc[1], a1, QQ);                               \
            ffma2(acc[2], a2, QQ); ffma2(acc[3], a3, QQ);                               \
            ffma2(acc[4], a4, QQ); ffma2(acc[5], a5, QQ);                               \
            ffma2(acc[6], a6, QQ); ffma2(acc[7], a7, QQ);                               \
            ffma2(acc[8], a8, QQ); ffma2(acc[9], a9, QQ);                               \
        } while (0)

        {
            const int UNR = 4;
            int k = k0;
            const int kmain = k0 + ((k1 - k0) / UNR) * UNR;
            float qv[UNR];
            if (k < kmain) {
                #pragma unroll
                for (int i = 0; i < UNR; i++) qv[i] = __ldcg(qr + (k + i) * HH + lane);
            }
            while (k < kmain) {
                const int knext = k + UNR;
                float qn[UNR];
                if (knext < kmain) {
                    #pragma unroll
                    for (int i = 0; i < UNR; i++) qn[i] = __ldcg(qr + (knext + i) * HH + lane);
                }
                #pragma unroll
                for (int i = 0; i < UNR; i++) {
                    const unsigned long long qq = pack2(qv[i], qv[i]);
                    ADJ_FMA(k + i, qq);
                }
                #pragma unroll
                for (int i = 0; i < UNR; i++) qv[i] = qn[i];
                k = knext;
            }
            for (; k < k1; ++k) {
                const float q1 = __ldcg(qr + k * HH + lane);
                const unsigned long long qq = pack2(q1, q1);
                ADJ_FMA(k, qq);
            }
        }
        #undef ADJ_FMA

        // ---- overlapped work: stage x_{t+1}, gates_t (pre-activated) ----
        const float* xcur = xsbuf + (t & 1) * ROWS * DD;
        float* xnext      = xsbuf + ((t + 1) & 1) * ROWS * DD;
        if (t + 1 < TT) {
            for (int e = tid; e < ROWS * DD; e += NTHREADS)
                xnext[e] = x[(size_t)(row0 + e / DD) * (TT * DD) + (t + 1) * DD + (e & (DD - 1))];
        }
        gates_act(tid, xcur, hs, g4s, W_ih, W_hh, b);

        // ---- reduction: 24 warps -> 4 slices, 6 chained rounds ----
        {
            const int s = wid & 3;
            float* rb = red + s * ROWS * HH;
            if (wid >= 20) {
                #pragma unroll
                for (int j = 0; j < ROWS / 2; j++) {
                    const float2 v = unpack2(acc[j]);
                    rb[(2 * j) * HH + lane]     = v.x;
                    rb[(2 * j + 1) * HH + lane] = v.y;
                }
            }
            __syncthreads();
            if (wid >= 16 && wid < 20) {
                #pragma unroll
                for (int j = 0; j < ROWS / 2; j++) {
                    const float2 v = unpack2(acc[j]);
                    rb[(2 * j) * HH + lane]     += v.x;
                    rb[(2 * j + 1) * HH + lane] += v.y;
                }
            }
            __syncthreads();
            if (wid >= 12 && wid < 16) {
                #pragma unroll
                for (int j = 0; j < ROWS / 2; j++) {
                    const float2 v = unpack2(acc[j]);
                    rb[(2 * j) * HH + lane]     += v.x;
                    rb[(2 * j + 1) * HH + lane] += v.y;
                }
            }
            __syncthreads();
            if (wid >= 8 && wid < 12) {
                #pragma unroll
                for (int j = 0; j < ROWS / 2; j++) {
                    const float2 v = unpack2(acc[j]);
                    rb[(2 * j) * HH + lane]     += v.x;
                    rb[(2 * j + 1) * HH + lane] += v.y;
                }
            }
            __syncthreads();
            if (wid >= 4 && wid < 8) {
                #pragma unroll
                for (int j = 0; j < ROWS / 2; j++) {
                    const float2 v = unpack2(acc[j]);
                    rb[(2 * j) * HH + lane]     += v.x;
                    rb[(2 * j + 1) * HH + lane] += v.y;
                }
            }
            __syncthreads();
            if (wid < 4) {
                #pragma unroll
                for (int j = 0; j < ROWS / 2; j++) {
                    const float2 v = unpack2(acc[j]);
                    rb[(2 * j) * HH + lane]     += v.x;
                    rb[(2 * j + 1) * HH + lane] += v.y;
                }
            }
        }
        __syncthreads();   // red + g4s complete

        // ---- LSTM epilogue (gates pre-activated) ----
        for (int e = tid; e < ROWS * HH; e += NTHREADS) {
            const int m = e >> 5, n = e & 31;
            const float aggv = red[m * HH + n]
                             + red[1 * ROWS * HH + m * HH + n]
                             + red[2 * ROWS * HH + m * HH + n]
                             + red[3 * ROWS * HH + m * HH + n];
            const float iv = g4s[m * G4 + n];
            const float fv = g4s[m * G4 + HH + n];
            const float gv = g4s[m * G4 + 2 * HH + n];
            const float ov = g4s[m * G4 + 3 * HH + n];
            const float cv = fv * (cs[e] + aggv) + iv * gv;
            cs[e] = cv;
            hs[e] = ov * tanh_f(cv);
        }
        __syncthreads();

        // ---- dense head ----
        if (tid < ROWS) {
            float a = b_d[0];
            #pragma unroll
            for (int n = 0; n < HH; n++) a += hs[tid * HH + n] * W_d[n];
            out[(size_t)(row0 + tid) * TT + t] = a;
        }

        if (t + 1 < TT) {
            q_prep(tid, row0, hs, W_q, b_q, g_q[(t + 1) & 1]);
            grid_barrier((unsigned)(t + 2));
        }
    }
}

extern "C" void kernel_launch(void* const* d_in, const int* in_sizes, int n_in,
                              void* d_out, int out_size) {
    (void)in_sizes; (void)n_in; (void)out_size;
    const float* x    = (const float*)d_in[0];
    const float* adj  = (const float*)d_in[1];
    const float* W_ih = (const float*)d_in[2];
    const float* W_hh = (const float*)d_in[3];
    const float* b    = (const float*)d_in[4];
    const float* W_q  = (const float*)d_in[5];
    const float* b_q  = (const float*)d_in[6];
    const float* W_d  = (const float*)d_in[7];
    const float* b_d  = (const float*)d_in[8];
    float* out = (float*)d_out;

    cudaFuncSetAttribute(rgcn_kernel,
                         cudaFuncAttributeMaxDynamicSharedMemorySize, SMEM_BYTES);
    rgcn_reset<<<1, 1>>>();
    rgcn_kernel<<<NCTA, NTHREADS, SMEM_BYTES>>>(x, adj, W_ih, W_hh, b,
                                                W_q, b_q, W_d, b_d, out);
}

// round 13
// speedup vs baseline: 1.1786x; 1.1786x over previous
#include <cuda_runtime.h>
#include <cuda_bf16.h>
#include <math.h>
#include <cstdint>

#define BSN 2500
#define TT  400
#define DD  16
#define HH  32
#define G4  128

#define MTILES   20
#define KSLICES  7
#define KSL      368          // k per slice (7*368 = 2576 >= 2500; disjoint slices)
#define KCH      23           // K16 chunks per slice
#define KTPAD    376          // padded k stride in B stage (bank spread)
#define KPAD     2576         // global q^T k stride (>= KSLICES*KSL), 16B-aligned rows
#define NCTA     140
#define NTHREADS 256
#define LCTAS    125
#define ROWS     20

// SMEM layout (bytes)
#define AFRAG_BYTES (8*KCH*32*16)              // 94208 per precision
#define SM_AHI   0
#define SM_ALO   AFRAG_BYTES
#define SM_BST   (2*AFRAG_BYTES)               // 188416
#define BST_BYTES (32*KTPAD*2)                 // 24064
#define SM_G4S   (SM_BST + BST_BYTES)          // 212480
#define SM_HS    (SM_G4S + ROWS*G4*4)          // 222720
#define SM_CS    (SM_HS + ROWS*HH*4)           // 225280
#define SM_XS    (SM_CS + ROWS*HH*4)           // 227840
#define SMEM_TOTAL (SM_XS + ROWS*DD*4 + 64)    // 229184

__device__ unsigned int g_bar;
__device__ __nv_bfloat16 g_qT_hi[32 * KPAD];   // q^T hi [n][k]; pads stay zero (never written)
__device__ __nv_bfloat16 g_qT_lo[32 * KPAD];   // q^T lo
__device__ float g_part[(size_t)NCTA * 128 * 32];  // K-split partials

// mma.sync m16n8k16 bf16 (baseline PTX, sm_80+, valid on sm_103 target)
#define MMA_BF16(d, a, b0_, b1_) \
    asm volatile("mma.sync.aligned.m16n8k16.row.col.f32.bf16.bf16.f32 " \
        "{%0,%1,%2,%3}, {%4,%5,%6,%7}, {%8,%9}, {%0,%1,%2,%3};" \
        : "+f"((d)[0]), "+f"((d)[1]), "+f"((d)[2]), "+f"((d)[3]) \
        : "r"((a).x), "r"((a).y), "r"((a).z), "r"((a).w), "r"(b0_), "r"(b1_))

__device__ __forceinline__ float sigmoid_f(float x) {
    return __fdividef(1.0f, 1.0f + __expf(-x));
}
__device__ __forceinline__ float tanh_f(float x) {
    return 1.0f - __fdividef(2.0f, __expf(2.0f * x) + 1.0f);
}
__device__ __forceinline__ void st_u16_cg(__nv_bfloat16* p, unsigned short v) {
    asm volatile("st.global.cg.u16 [%0], %1;" :: "l"(p), "h"(v) : "memory");
}

__device__ __forceinline__ void grid_barrier(unsigned epoch) {
    __threadfence();
    __syncthreads();
    if (threadIdx.x == 0) {
        atomicAdd(&g_bar, 1u);
        const unsigned target = epoch * (unsigned)NCTA;
        unsigned v;
        do {
            asm volatile("ld.acquire.gpu.global.u32 %0, [%1];" : "=r"(v) : "l"(&g_bar) : "memory");
        } while (v < target);
    }
    __syncthreads();
}

__global__ void rgcn_reset() { g_bar = 0u; }

// load adj pair (r, k), (r, k+1); split to bf16 hi/lo packed pairs
__device__ __forceinline__ void split_pair(const float* __restrict__ adj, int r, int k,
                                           uint32_t& h, uint32_t& l) {
    float xv = (r < BSN && k     < BSN) ? __ldg(&adj[(size_t)r * BSN + k])     : 0.0f;
    float yv = (r < BSN && k + 1 < BSN) ? __ldg(&adj[(size_t)r * BSN + k + 1]) : 0.0f;
    __nv_bfloat16 hx = __float2bfloat16(xv), hy = __float2bfloat16(yv);
    __nv_bfloat16 lx = __float2bfloat16(xv - __bfloat162float(hx));
    __nv_bfloat16 ly = __float2bfloat16(yv - __bfloat162float(hy));
    h = (uint32_t)__bfloat16_as_ushort(hx) | ((uint32_t)__bfloat16_as_ushort(hy) << 16);
    l = (uint32_t)__bfloat16_as_ushort(lx) | ((uint32_t)__bfloat16_as_ushort(ly) << 16);
}

// gates pre-activated into g4s (256 threads: 2 groups x 10 rows)
__device__ __forceinline__ void gates_act(
    int tid, const float* xs, const float* hs, float* g4s,
    const float* __restrict__ W_ih, const float* __restrict__ W_hh,
    const float* __restrict__ b)
{
    const int j  = tid & 127;
    const int m0 = (tid >> 7) * 10;
    float a10[10];
    const float bj = b[j];
    #pragma unroll
    for (int mm = 0; mm < 10; mm++) a10[mm] = bj;
    #pragma unroll
    for (int kk = 0; kk < HH; kk++) {
        const float w = W_hh[kk * G4 + j];
        #pragma unroll
        for (int mm = 0; mm < 10; mm++) a10[mm] += hs[(m0 + mm) * HH + kk] * w;
    }
    #pragma unroll
    for (int d = 0; d < DD; d++) {
        const float w = W_ih[d * G4 + j];
        #pragma unroll
        for (int mm = 0; mm < 10; mm++) a10[mm] += xs[(m0 + mm) * DD + d] * w;
    }
    const int sect = j >> 5;
    #pragma unroll
    for (int mm = 0; mm < 10; mm++) {
        const float v = (sect == 2) ? tanh_f(a10[mm]) : sigmoid_f(a10[mm]);
        g4s[(m0 + mm) * G4 + j] = v;
    }
}

// q = tanh(h@W_q + b_q), bf16 hi/lo split, transposed to global
__device__ __forceinline__ void q_prep(
    int tid, int row0, const float* hs,
    const float* __restrict__ W_q, const float* __restrict__ b_q)
{
    for (int e = tid; e < ROWS * HH; e += NTHREADS) {
        const int m = e >> 5, n = e & 31;
        float a = b_q[n];
        #pragma unroll
        for (int kk = 0; kk < HH; kk++) a += hs[m * HH + kk] * W_q[kk * HH + n];
        const float q = tanh_f(a);
        const __nv_bfloat16 hi = __float2bfloat16(q);
        const __nv_bfloat16 lo = __float2bfloat16(q - __bfloat162float(hi));
        const int r = row0 + m;
        st_u16_cg(&g_qT_hi[n * KPAD + r], __bfloat16_as_ushort(hi));
        st_u16_cg(&g_qT_lo[n * KPAD + r], __bfloat16_as_ushort(lo));
    }
}

__global__ void __launch_bounds__(NTHREADS, 1)
rgcn_kernel(const float* __restrict__ x,    const float* __restrict__ adj,
            const float* __restrict__ W_ih, const float* __restrict__ W_hh,
            const float* __restrict__ b,    const float* __restrict__ W_q,
            const float* __restrict__ b_q,  const float* __restrict__ W_d,
            const float* __restrict__ b_d,  float* __restrict__ out)
{
    extern __shared__ char smem[];
    float* g4s = (float*)(smem + SM_G4S);
    float* hs  = (float*)(smem + SM_HS);
    float* cs  = (float*)(smem + SM_CS);
    float* xs  = (float*)(smem + SM_XS);

    const int tid  = threadIdx.x;
    const int lane = tid & 31;
    const int wid  = tid >> 5;
    const int bid  = blockIdx.x;
    const int mtg  = bid / KSLICES;       // global M-tile 0..19
    const int ksl  = bid % KSLICES;       // K-slice 0..6
    const bool lstm = (bid < LCTAS);
    const int row0 = bid * ROWS;
    const int g    = lane >> 2;           // fragment group
    const int tig  = lane & 3;            // thread-in-group

    // ---- prologue: build A fragments (bf16 hi/lo), ready for LDS.128 ----
    for (int idx = tid; idx < 8 * KCH * 32; idx += NTHREADS) {
        const int l  = idx & 31;
        const int c  = (idx >> 5) % KCH;
        const int mt = idx / (KCH * 32);
        const int lg = l >> 2, lt = l & 3;
        const int r0 = mtg * 128 + mt * 16 + lg;
        const int kb = ksl * KSL + c * 16 + lt * 2;
        uint32_t h0, h1, h2, h3, l0, l1, l2, l3;
        split_pair(adj, r0,     kb,     h0, l0);   // a0
        split_pair(adj, r0 + 8, kb,     h1, l1);   // a1
        split_pair(adj, r0,     kb + 8, h2, l2);   // a2
        split_pair(adj, r0 + 8, kb + 8, h3, l3);   // a3
        *(uint4*)(smem + SM_AHI + (size_t)idx * 16) = make_uint4(h0, h1, h2, h3);
        *(uint4*)(smem + SM_ALO + (size_t)idx * 16) = make_uint4(l0, l1, l2, l3);
    }

    // ---- prologue: LSTM init + gates(0) + q_0 ----
    if (lstm) {
        for (int e = tid; e < ROWS * HH; e += NTHREADS) { hs[e] = 0.0f; cs[e] = 0.0f; }
        for (int e = tid; e < ROWS * DD; e += NTHREADS)
            xs[e] = x[(size_t)(row0 + e / DD) * (TT * DD) + (e & (DD - 1))];
    }
    __syncthreads();
    if (lstm) {
        gates_act(tid, xs, hs, g4s, W_ih, W_hh, b);
        q_prep(tid, row0, hs, W_q, b_q);
    }
    grid_barrier(1);

    // stage full 368-k slice of q^T (hi or lo): 46 uint4 (= 368 bf16) per n-column
    #define STAGE_B(SRC) do { \
        for (int i = tid; i < 32 * 2 * KCH; i += NTHREADS) { \
            const int n = i / (2 * KCH), kc = i % (2 * KCH); \
            const uint4 v = __ldcg((const uint4*)((SRC) + (size_t)n * KPAD + ksl * KSL + kc * 8)); \
            *(uint4*)(smem + SM_BST + (size_t)n * (KTPAD * 2) + kc * 16) = v; \
        } } while (0)

    // ================= time loop =================
    for (int t = 0; t < TT; ++t) {
        float D[4][4];
        #pragma unroll
        for (int n = 0; n < 4; n++) { D[n][0] = D[n][1] = D[n][2] = D[n][3] = 0.0f; }

        // ---- pass 1: B_hi staged; A_hi*B_hi + A_lo*B_hi ----
        STAGE_B(g_qT_hi);
        __syncthreads();
        #pragma unroll 1
        for (int c = 0; c < KCH; ++c) {
            const uint4 ah = *(const uint4*)(smem + SM_AHI + (size_t)((wid * KCH + c) * 32 + lane) * 16);
            const uint4 al = *(const uint4*)(smem + SM_ALO + (size_t)((wid * KCH + c) * 32 + lane) * 16);
            uint32_t b0[4], b1[4];
            #pragma unroll
            for (int n = 0; n < 4; n++) {
                const char* bp = smem + SM_BST + (size_t)(n * 8 + g) * (KTPAD * 2)
                               + (size_t)(c * 16 + tig * 2) * 2;
                b0[n] = *(const uint32_t*)bp;
                b1[n] = *(const uint32_t*)(bp + 16);
            }
            #pragma unroll
            for (int n = 0; n < 4; n++) MMA_BF16(D[n], ah, b0[n], b1[n]);
            #pragma unroll
            for (int n = 0; n < 4; n++) MMA_BF16(D[n], al, b0[n], b1[n]);
        }
        __syncthreads();

        // ---- pass 2: B_lo staged; A_hi*B_lo ----
        STAGE_B(g_qT_lo);
        __syncthreads();
        #pragma unroll 1
        for (int c = 0; c < KCH; ++c) {
            const uint4 ah = *(const uint4*)(smem + SM_AHI + (size_t)((wid * KCH + c) * 32 + lane) * 16);
            uint32_t b0[4], b1[4];
            #pragma unroll
            for (int n = 0; n < 4; n++) {
                const char* bp = smem + SM_BST + (size_t)(n * 8 + g) * (KTPAD * 2)
                               + (size_t)(c * 16 + tig * 2) * 2;
                b0[n] = *(const uint32_t*)bp;
                b1[n] = *(const uint32_t*)(bp + 16);
            }
            #pragma unroll
            for (int n = 0; n < 4; n++) MMA_BF16(D[n], ah, b0[n], b1[n]);
        }

        // ---- store partials ----
        {
            const int rl = wid * 16 + g;
            float* pb = g_part + ((size_t)bid * 128 + rl) * 32;
            #pragma unroll
            for (int n = 0; n < 4; n++) {
                const int col = n * 8 + tig * 2;
                __stcg((float2*)(pb + col),          make_float2(D[n][0], D[n][1]));
                __stcg((float2*)(pb + 8 * 32 + col), make_float2(D[n][2], D[n][3]));
            }
        }
        grid_barrier(2 + 2 * t);

        // ---- phase 2: gather + LSTM (CTAs 0..124) ----
        if (lstm) {
            for (int e = tid; e < ROWS * HH; e += NTHREADS) {
                const int m = e >> 5, n = e & 31;
                const int r = row0 + m;
                const int mtr = r >> 7, mr = r & 127;
                float aggv = 0.0f;
                #pragma unroll
                for (int s = 0; s < KSLICES; s++)
                    aggv += __ldcg(&g_part[(((size_t)mtr * KSLICES + s) * 128 + mr) * 32 + n]);
                const float iv = g4s[m * G4 + n];
                const float fv = g4s[m * G4 + HH + n];
                const float gv = g4s[m * G4 + 2 * HH + n];
                const float ov = g4s[m * G4 + 3 * HH + n];
                const float cv = fv * (cs[e] + aggv) + iv * gv;
                cs[e] = cv;
                hs[e] = ov * tanh_f(cv);
            }
            if (t + 1 < TT) {
                for (int e = tid; e < ROWS * DD; e += NTHREADS)
                    xs[e] = x[(size_t)(row0 + e / DD) * (TT * DD) + (t + 1) * DD + (e & (DD - 1))];
            }
            __syncthreads();
            if (tid < ROWS) {
                float a = b_d[0];
                #pragma unroll
                for (int n = 0; n < HH; n++) a += hs[tid * HH + n] * W_d[n];
                out[(size_t)(row0 + tid) * TT + t] = a;
            }
            if (t + 1 < TT) {
                gates_act(tid, xs, hs, g4s, W_ih, W_hh, b);
                q_prep(tid, row0, hs, W_q, b_q);
            }
        }
        if (t + 1 < TT) grid_barrier(3 + 2 * t);
    }
    #undef STAGE_B
}

extern "C" void kernel_launch(void* const* d_in, const int* in_sizes, int n_in,
                              void* d_out, int out_size) {
    (void)in_sizes; (void)n_in; (void)out_size;
    const float* x    = (const float*)d_in[0];
    const float* adj  = (const float*)d_in[1];
    const float* W_ih = (const float*)d_in[2];
    const float* W_hh = (const float*)d_in[3];
    const float* b    = (const float*)d_in[4];
    const float* W_q  = (const float*)d_in[5];
    const float* b_q  = (const float*)d_in[6];
    const float* W_d  = (const float*)d_in[7];
    const float* b_d  = (const float*)d_in[8];
    float* out = (float*)d_out;

    cudaFuncSetAttribute(rgcn_kernel,
                         cudaFuncAttributeMaxDynamicSharedMemorySize, SMEM_TOTAL);
    rgcn_reset<<<1, 1>>>();
    rgcn_kernel<<<NCTA, NTHREADS, SMEM_TOTAL>>>(x, adj, W_ih, W_hh, b,
                                                W_q, b_q, W_d, b_d, out);
}

// round 14
// speedup vs baseline: 1.4952x; 1.2686x over previous
#include <cuda_runtime.h>
#include <cuda_bf16.h>
#include <math.h>
#include <cstdint>

#define BSN 2500
#define TT  400
#define DD  16
#define HH  32
#define G4  128

#define MTILES   20
#define KSLICES  7
#define KSL      368          // 7*368 = 2576 >= 2500
#define KCH      23           // K16 chunks per slice
#define KTPAD    376          // padded k stride in B stage (conflict-free)
#define KPAD     2576         // global q^T k stride
#define NCTA     140
#define NTHREADS 512
#define LCTAS    125
#define ROWS     20

// SMEM layout (bytes)
#define AFRAG_BYTES (8*KCH*32*16)              // 94208 (A_hi only)
#define SM_AHI   0
#define SM_BHI   AFRAG_BYTES                   // 94208
#define BST_BYTES (32*KTPAD*2)                 // 24064
#define SM_BLO   (SM_BHI + BST_BYTES)          // 118272
#define SM_G4S   (SM_BLO + BST_BYTES)          // 142336
#define SM_HS    (SM_G4S + ROWS*G4*4)          // 152576
#define SM_CS    (SM_HS + ROWS*HH*4)           // 155136
#define SM_XS    (SM_CS + ROWS*HH*4)           // 157696
#define SMEM_TOTAL (SM_XS + ROWS*DD*4 + 64)    // 159040

__device__ unsigned int g_bar;
__device__ __nv_bfloat16 g_qT_hi[32 * KPAD];
__device__ __nv_bfloat16 g_qT_lo[32 * KPAD];
__device__ uint4 g_alo[(size_t)NCTA * 8 * KCH * 32];      // A_lo fragments (13.2 MB)
__device__ float g_part[(size_t)NCTA * 2 * 128 * 32];     // partials per (CTA, k-half)

#define MMA_BF16(d, a, b0_, b1_) \
    asm volatile("mma.sync.aligned.m16n8k16.row.col.f32.bf16.bf16.f32 " \
        "{%0,%1,%2,%3}, {%4,%5,%6,%7}, {%8,%9}, {%0,%1,%2,%3};" \
        : "+f"((d)[0]), "+f"((d)[1]), "+f"((d)[2]), "+f"((d)[3]) \
        : "r"((a).x), "r"((a).y), "r"((a).z), "r"((a).w), "r"(b0_), "r"(b1_))

__device__ __forceinline__ float sigmoid_f(float x) {
    return __fdividef(1.0f, 1.0f + __expf(-x));
}
__device__ __forceinline__ float tanh_f(float x) {
    return 1.0f - __fdividef(2.0f, __expf(2.0f * x) + 1.0f);
}
__device__ __forceinline__ void st_u16_cg(__nv_bfloat16* p, unsigned short v) {
    asm volatile("st.global.cg.u16 [%0], %1;" :: "l"(p), "h"(v) : "memory");
}

__device__ __forceinline__ void grid_barrier(unsigned epoch) {
    __threadfence();
    __syncthreads();
    if (threadIdx.x == 0) {
        atomicAdd(&g_bar, 1u);
        const unsigned target = epoch * (unsigned)NCTA;
        unsigned v;
        do {
            asm volatile("ld.acquire.gpu.global.u32 %0, [%1];" : "=r"(v) : "l"(&g_bar) : "memory");
        } while (v < target);
    }
    __syncthreads();
}

__global__ void rgcn_reset() { g_bar = 0u; }

__device__ __forceinline__ void split_pair(const float* __restrict__ adj, int r, int k,
                                           uint32_t& h, uint32_t& l) {
    float xv = (r < BSN && k     < BSN) ? __ldg(&adj[(size_t)r * BSN + k])     : 0.0f;
    float yv = (r < BSN && k + 1 < BSN) ? __ldg(&adj[(size_t)r * BSN + k + 1]) : 0.0f;
    __nv_bfloat16 hx = __float2bfloat16(xv), hy = __float2bfloat16(yv);
    __nv_bfloat16 lx = __float2bfloat16(xv - __bfloat162float(hx));
    __nv_bfloat16 ly = __float2bfloat16(yv - __bfloat162float(hy));
    h = (uint32_t)__bfloat16_as_ushort(hx) | ((uint32_t)__bfloat16_as_ushort(hy) << 16);
    l = (uint32_t)__bfloat16_as_ushort(lx) | ((uint32_t)__bfloat16_as_ushort(ly) << 16);
}

// gates pre-activated into g4s (512 threads: 4 groups x 5 rows)
__device__ __forceinline__ void gates_act(
    int tid, const float* xs, const float* hs, float* g4s,
    const float* __restrict__ W_ih, const float* __restrict__ W_hh,
    const float* __restrict__ b)
{
    const int j  = tid & 127;
    const int m0 = (tid >> 7) * 5;
    float a5[5];
    const float bj = b[j];
    #pragma unroll
    for (int mm = 0; mm < 5; mm++) a5[mm] = bj;
    #pragma unroll
    for (int kk = 0; kk < HH; kk++) {
        const float w = W_hh[kk * G4 + j];
        #pragma unroll
        for (int mm = 0; mm < 5; mm++) a5[mm] += hs[(m0 + mm) * HH + kk] * w;
    }
    #pragma unroll
    for (int d = 0; d < DD; d++) {
        const float w = W_ih[d * G4 + j];
        #pragma unroll
        for (int mm = 0; mm < 5; mm++) a5[mm] += xs[(m0 + mm) * DD + d] * w;
    }
    const int sect = j >> 5;
    #pragma unroll
    for (int mm = 0; mm < 5; mm++) {
        const float v = (sect == 2) ? tanh_f(a5[mm]) : sigmoid_f(a5[mm]);
        g4s[(m0 + mm) * G4 + j] = v;
    }
}

__device__ __forceinline__ void q_prep(
    int tid, int row0, const float* hs,
    const float* __restrict__ W_q, const float* __restrict__ b_q)
{
    for (int e = tid; e < ROWS * HH; e += NTHREADS) {
        const int m = e >> 5, n = e & 31;
        float a = b_q[n];
        #pragma unroll
        for (int kk = 0; kk < HH; kk++) a += hs[m * HH + kk] * W_q[kk * HH + n];
        const float q = tanh_f(a);
        const __nv_bfloat16 hi = __float2bfloat16(q);
        const __nv_bfloat16 lo = __float2bfloat16(q - __bfloat162float(hi));
        const int r = row0 + m;
        st_u16_cg(&g_qT_hi[n * KPAD + r], __bfloat16_as_ushort(hi));
        st_u16_cg(&g_qT_lo[n * KPAD + r], __bfloat16_as_ushort(lo));
    }
}

__global__ void __launch_bounds__(NTHREADS, 1)
rgcn_kernel(const float* __restrict__ x,    const float* __restrict__ adj,
            const float* __restrict__ W_ih, const float* __restrict__ W_hh,
            const float* __restrict__ b,    const float* __restrict__ W_q,
            const float* __restrict__ b_q,  const float* __restrict__ W_d,
            const float* __restrict__ b_d,  float* __restrict__ out)
{
    extern __shared__ char smem[];
    float* g4s = (float*)(smem + SM_G4S);
    float* hs  = (float*)(smem + SM_HS);
    float* cs  = (float*)(smem + SM_CS);
    float* xs  = (float*)(smem + SM_XS);

    const int tid  = threadIdx.x;
    const int lane = tid & 31;
    const int wid  = tid >> 5;
    const int bid  = blockIdx.x;
    const int mtg  = bid / KSLICES;
    const int ksl  = bid % KSLICES;
    const bool lstm = (bid < LCTAS);
    const int row0 = bid * ROWS;
    const int g    = lane >> 2;
    const int tig  = lane & 3;
    const int msub  = wid & 7;            // m16 subtile within 128-row tile
    const int khalf = wid >> 3;           // k-half: chunks [0,12) / [12,23)

    // ---- prologue: A_hi frags -> SMEM, A_lo frags -> global ----
    for (int idx = tid; idx < 8 * KCH * 32; idx += NTHREADS) {
        const int l  = idx & 31;
        const int c  = (idx >> 5) % KCH;
        const int mt = idx / (KCH * 32);
        const int lg = l >> 2, lt = l & 3;
        const int r0 = mtg * 128 + mt * 16 + lg;
        const int kb = ksl * KSL + c * 16 + lt * 2;
        uint32_t h0, h1, h2, h3, l0, l1, l2, l3;
        split_pair(adj, r0,     kb,     h0, l0);
        split_pair(adj, r0 + 8, kb,     h1, l1);
        split_pair(adj, r0,     kb + 8, h2, l2);
        split_pair(adj, r0 + 8, kb + 8, h3, l3);
        *(uint4*)(smem + SM_AHI + (size_t)idx * 16) = make_uint4(h0, h1, h2, h3);
        g_alo[(size_t)bid * (8 * KCH * 32) + idx] = make_uint4(l0, l1, l2, l3);
    }

    if (lstm) {
        for (int e = tid; e < ROWS * HH; e += NTHREADS) { hs[e] = 0.0f; cs[e] = 0.0f; }
        for (int e = tid; e < ROWS * DD; e += NTHREADS)
            xs[e] = x[(size_t)(row0 + e / DD) * (TT * DD) + (e & (DD - 1))];
    }
    __syncthreads();
    if (lstm) {
        gates_act(tid, xs, hs, g4s, W_ih, W_hh, b);
        q_prep(tid, row0, hs, W_q, b_q);
    }
    grid_barrier(1);

    const int cbeg = khalf ? 12 : 0;
    const int cend = khalf ? KCH : 12;
    const uint4* aloc = &g_alo[(size_t)(bid * 8 + msub) * (KCH * 32)];

    // ================= time loop =================
    for (int t = 0; t < TT; ++t) {
        // ---- stage B_hi + B_lo together (one sync) ----
        for (int i = tid; i < 32 * 2 * KCH; i += NTHREADS) {
            const int n = i / (2 * KCH), kc = i % (2 * KCH);
            const uint4 vh = __ldcg((const uint4*)(g_qT_hi + (size_t)n * KPAD + ksl * KSL + kc * 8));
            const uint4 vl = __ldcg((const uint4*)(g_qT_lo + (size_t)n * KPAD + ksl * KSL + kc * 8));
            *(uint4*)(smem + SM_BHI + (size_t)n * (KTPAD * 2) + kc * 16) = vh;
            *(uint4*)(smem + SM_BLO + (size_t)n * (KTPAD * 2) + kc * 16) = vl;
        }
        __syncthreads();

        // ---- fused 3-term MMA over this warp's k chunks ----
        float D[4][4];
        #pragma unroll
        for (int n = 0; n < 4; n++) { D[n][0] = D[n][1] = D[n][2] = D[n][3] = 0.0f; }

        uint4 alv = __ldcg(&aloc[cbeg * 32 + lane]);   // prefetch first A_lo
        #pragma unroll 1
        for (int c = cbeg; c < cend; ++c) {
            const uint4 ah = *(const uint4*)(smem + SM_AHI + (size_t)((msub * KCH + c) * 32 + lane) * 16);
            const uint4 al = alv;
            if (c + 1 < cend) alv = __ldcg(&aloc[(c + 1) * 32 + lane]);
            #pragma unroll
            for (int n = 0; n < 4; n++) {
                const char* bph = smem + SM_BHI + (size_t)(n * 8 + g) * (KTPAD * 2)
                                + (size_t)(c * 16 + tig * 2) * 2;
                const char* bpl = smem + SM_BLO + (size_t)(n * 8 + g) * (KTPAD * 2)
                                + (size_t)(c * 16 + tig * 2) * 2;
                const uint32_t bh0 = *(const uint32_t*)bph;
                const uint32_t bh1 = *(const uint32_t*)(bph + 16);
                const uint32_t bl0 = *(const uint32_t*)bpl;
                const uint32_t bl1 = *(const uint32_t*)(bpl + 16);
                MMA_BF16(D[n], ah, bh0, bh1);
                MMA_BF16(D[n], al, bh0, bh1);
                MMA_BF16(D[n], ah, bl0, bl1);
            }
        }

        // ---- store partials (slot = bid*2 + khalf) ----
        {
            const int rl = msub * 16 + g;
            float* pb = g_part + ((size_t)(bid * 2 + khalf) * 128 + rl) * 32;
            #pragma unroll
            for (int n = 0; n < 4; n++) {
                const int col = n * 8 + tig * 2;
                __stcg((float2*)(pb + col),          make_float2(D[n][0], D[n][1]));
                __stcg((float2*)(pb + 8 * 32 + col), make_float2(D[n][2], D[n][3]));
            }
        }
        grid_barrier(2 + 2 * t);

        // ---- gather + LSTM (CTAs 0..124) ----
        if (lstm) {
            for (int e = tid; e < ROWS * HH; e += NTHREADS) {
                const int m = e >> 5, n = e & 31;
                const int r = row0 + m;
                const int mtr = r >> 7, mr = r & 127;
                float aggv = 0.0f;
                #pragma unroll
                for (int s = 0; s < KSLICES; s++) {
                    const size_t base = (size_t)((mtr * KSLICES + s) * 2) * (128 * 32) + (size_t)mr * 32 + n;
                    aggv += __ldcg(&g_part[base]);
                    aggv += __ldcg(&g_part[base + 128 * 32]);
                }
                const float iv = g4s[m * G4 + n];
                const float fv = g4s[m * G4 + HH + n];
                const float gv = g4s[m * G4 + 2 * HH + n];
                const float ov = g4s[m * G4 + 3 * HH + n];
                const float cv = fv * (cs[e] + aggv) + iv * gv;
                cs[e] = cv;
                hs[e] = ov * tanh_f(cv);
            }
            if (t + 1 < TT) {
                for (int e = tid; e < ROWS * DD; e += NTHREADS)
                    xs[e] = x[(size_t)(row0 + e / DD) * (TT * DD) + (t + 1) * DD + (e & (DD - 1))];
            }
            __syncthreads();
            if (tid < ROWS) {
                float a = b_d[0];
                #pragma unroll
                for (int n = 0; n < HH; n++) a += hs[tid * HH + n] * W_d[n];
                out[(size_t)(row0 + tid) * TT + t] = a;
            }
            if (t + 1 < TT) {
                gates_act(tid, xs, hs, g4s, W_ih, W_hh, b);
                q_prep(tid, row0, hs, W_q, b_q);
            }
        }
        if (t + 1 < TT) grid_barrier(3 + 2 * t);
    }
}

extern "C" void kernel_launch(void* const* d_in, const int* in_sizes, int n_in,
                              void* d_out, int out_size) {
    (void)in_sizes; (void)n_in; (void)out_size;
    const float* x    = (const float*)d_in[0];
    const float* adj  = (const float*)d_in[1];
    const float* W_ih = (const float*)d_in[2];
    const float* W_hh = (const float*)d_in[3];
    const float* b    = (const float*)d_in[4];
    const float* W_q  = (const float*)d_in[5];
    const float* b_q  = (const float*)d_in[6];
    const float* W_d  = (const float*)d_in[7];
    const float* b_d  = (const float*)d_in[8];
    float* out = (float*)d_out;

    cudaFuncSetAttribute(rgcn_kernel,
                         cudaFuncAttributeMaxDynamicSharedMemorySize, SMEM_TOTAL);
    rgcn_reset<<<1, 1>>>();
    rgcn_kernel<<<NCTA, NTHREADS, SMEM_TOTAL>>>(x, adj, W_ih, W_hh, b,
                                                W_q, b_q, W_d, b_d, out);
}